// round 8
// baseline (speedup 1.0000x reference)
#include <cuda_runtime.h>

// Problem shapes (fixed by the dataset)
constexpr int B  = 8;
constexpr int H  = 512, W  = 512;
constexpr int HO = 1024, WO = 1024;
constexpr int FPY = 514;             // padded rows: y coords -1..512
constexpr int FPX = 516;             // padded row stride (514 valid + 2 pad, float4-aligned)
constexpr int NPIX = B * HO * WO;    // 8388608 output pixels
constexpr int NQUAD = NPIX / 4;      // 2097152 output quads

// ---- fix kernel tiling ----
constexpr int TX = 128, TY = 16;     // output tile per block (padded coords)
constexpr int CTILES = 5;            // ceil(514/128)
constexpr int RTILES = 33;           // ceil(514/16)
constexpr int FBLOCKS = B * CTILES * RTILES;   // 1320
constexpr int SR  = TY + 2;          // 18 smem rows (input halo)
constexpr int SCN = TX + 2;          // 130 needed smem cols
constexpr int SC  = 132;             // padded smem row stride (floats)

// ---- sample kernel ----
constexpr int SAMPLE_BLOCKS  = 888;  // 6 CTAs/SM, single persistent wave
constexpr int SAMPLE_THREADS = 256;

// Precomputed "fixed" depth map, padded domain. 8*514*516*4 B = 8.49 MB (L2-resident).
__device__ float4 g_fix4[B * FPY * (FPX / 4)];

// ---------------- pass 1: fix map (smem-tiled stencil) ----------------
// First-valid among 9 offsets, reference order:
// (0,0), (-1,-1),(-1,0),(-1,1),(0,-1),(0,1),(1,-1),(1,0),(1,1)
// Output at padded (py,px) reads input rows py-2..py, cols px-2..px.
__global__ void __launch_bounds__(256) fix_kernel(const float* __restrict__ depth) {
    __shared__ float s[SR * SC];
    int bx = blockIdx.x;
    int ct = bx % CTILES;
    int rt = (bx / CTILES) % RTILES;
    int b  = bx / (CTILES * RTILES);
    int px0 = ct * TX;
    int py0 = rt * TY;
    const float* img = depth + b * (H * W);
    int tid = threadIdx.x;

    // coalesced halo load: input rows py0-2 .. py0+15, cols px0-2 .. px0+127
    for (int idx = tid; idx < SR * SCN; idx += 256) {
        int r = idx / SCN, c = idx - r * SCN;
        int gr = py0 - 2 + r;
        int gc = px0 - 2 + c;
        bool inb = ((unsigned)gr < (unsigned)H) & ((unsigned)gc < (unsigned)W);
        s[r * SC + c] = inb ? __ldg(img + gr * W + gc) : 0.0f;
    }
    __syncthreads();

    int cl   = tid & 127;            // column within tile
    int half = tid >> 7;             // 0: rows 0..7, 1: rows 8..15
    int px   = px0 + cl;
    if (px < 514) {
        int r0 = half * 8;           // smem row base (taps r0..r0+2 for first output)
        float a0[3], a1[3], a2[3];
#pragma unroll
        for (int k = 0; k < 3; k++) {
            a0[k] = s[(r0 + 0) * SC + cl + k];
            a1[k] = s[(r0 + 1) * SC + cl + k];
            a2[k] = s[(r0 + 2) * SC + cl + k];
        }
        float* gfix = (float*)g_fix4 + b * (FPY * FPX);
#pragma unroll
        for (int j = 0; j < 8; j++) {
            int py = py0 + half * 8 + j;
            if (py < 514) {
                // a0 = input row py-2, a1 = py-1 (center row), a2 = py
                float c9[9] = { a1[1],
                                a0[0], a0[1], a0[2],
                                a1[0],        a1[2],
                                a2[0], a2[1], a2[2] };
                float v = 0.0f;
#pragma unroll
                for (int k = 8; k >= 0; k--) {
                    if (c9[k] != 0.0f) v = c9[k];   // first-valid via reverse last-write
                }
                gfix[py * FPX + px] = v;
            }
            if (j < 7) {
#pragma unroll
                for (int k = 0; k < 3; k++) {
                    a0[k] = a1[k];
                    a1[k] = a2[k];
                    a2[k] = s[(r0 + 3 + j) * SC + cl + k];
                }
            }
        }
    }
}

// ---------------- pass 2: sampler ----------------
// 4 independent gathers for quad q; grid values ga,gb.
__device__ __forceinline__ void do_quad(int q, float4 ga, float4 gb,
                                        float4* __restrict__ out) {
    int b = q >> 18;                          // quads never span batches (HO*WO = 1<<20)
    const float* fixp = (const float*)g_fix4 + b * (FPY * FPX);
    float gx[4] = {ga.x, ga.z, gb.x, gb.z};
    float gy[4] = {ga.y, ga.w, gb.y, gb.w};
    float v[4];
#pragma unroll
    for (int i = 0; i < 4; i++) {
        // ((g+1)*0.5)*511 == round_fp32(g+1) * 255.5 exactly (×0.5 exact);
        // __float2int_rn = ties-to-even = jnp.round
        float xf = __fmul_rn(__fadd_rn(gx[i], 1.0f), 255.5f);
        float yf = __fmul_rn(__fadd_rn(gy[i], 1.0f), 255.5f);
        int ix = __float2int_rn(xf) + 1;      // padded coords
        int iy = __float2int_rn(yf) + 1;
        bool inb = ((unsigned)ix < 514u) & ((unsigned)iy < 514u);
        v[i] = inb ? __ldg(fixp + iy * FPX + ix) : 0.0f;
    }
    float4 o = {v[0], v[1], v[2], v[3]};
    __stcs(out + q, o);
}

// Grid-stride, 4 px/iteration, next iteration's grid prefetched while the
// current gathers are in flight. Grid loads use DEFAULT cache policy: the
// whole working set (~108 MB) fits L2, so grid stays L2-resident across
// replays (577 -> ~250 cyc exposed latency at each pipeline head).
__global__ void __launch_bounds__(SAMPLE_THREADS)
sample_kernel(const float4* __restrict__ grid, float4* __restrict__ out) {
    const int stride = SAMPLE_BLOCKS * SAMPLE_THREADS;
    int q = blockIdx.x * SAMPLE_THREADS + threadIdx.x;
    if (q >= NQUAD) return;

    float4 ga = __ldg(grid + 2 * q);
    float4 gb = __ldg(grid + 2 * q + 1);

    int qn = q + stride;
    while (qn < NQUAD) {
        float4 na = __ldg(grid + 2 * qn);      // prefetch next (overlaps gathers below)
        float4 nb = __ldg(grid + 2 * qn + 1);
        do_quad(q, ga, gb, out);
        q = qn; qn += stride;
        ga = na; gb = nb;
    }
    do_quad(q, ga, gb, out);
}

extern "C" void kernel_launch(void* const* d_in, const int* in_sizes, int n_in,
                              void* d_out, int out_size) {
    const float*  depth = (const float*)d_in[0];   // (B,1,H,W) f32
    const float4* grid  = (const float4*)d_in[1];  // (B,Ho,Wo,2) f32 as float4
    float4*       out   = (float4*)d_out;          // (B,1,Ho,Wo) f32 as float4

    fix_kernel<<<FBLOCKS, 256>>>(depth);
    sample_kernel<<<SAMPLE_BLOCKS, SAMPLE_THREADS>>>(grid, out);
}

// round 9
// speedup vs baseline: 1.1268x; 1.1268x over previous
#include <cuda_runtime.h>
#include <cuda_fp16.h>

// Problem shapes (fixed by the dataset)
constexpr int B  = 8;
constexpr int H  = 512, W  = 512;
constexpr int HO = 1024, WO = 1024;
constexpr int FPY = 514;             // padded rows: y coords -1..512
constexpr int FPX = 516;             // padded row stride (8B-aligned rows for half)
constexpr int TPR = 129;             // fix col-groups per row (129*4 = 516)
constexpr int NPIX = B * HO * WO;
constexpr int NFIXT = B * FPY * TPR;
constexpr int QPB  = (HO * WO) / 4;  // 262144 quads per batch

constexpr int SAMPLE_THREADS = 256;
constexpr int SAMPLE_BLOCKS  = 888;  // 6 CTAs/SM, single wave

// Precomputed "fixed" depth map in fp16, padded domain.
// 8 * 514 * 516 * 2 B = 4.24 MB; per-batch slice 531 KB (partially L1-resident).
__device__ __half g_fixh[B * FPY * FPX];

// ---------------- pass 1: fix map ----------------
// Load 6 input floats covering columns [px0-2, px0+3] of `row` (0 if OOB).
__device__ __forceinline__ void load_row6(const float* __restrict__ img, int row,
                                          int px0, float v[6]) {
    if ((unsigned)row >= (unsigned)H) {
        v[0] = v[1] = v[2] = v[3] = v[4] = v[5] = 0.0f;
        return;
    }
    const float* rp = img + row * W;
    if (px0 >= 4 && px0 <= 508) {
        float4 a = *(const float4*)(rp + px0 - 4);
        float4 b = *(const float4*)(rp + px0);
        v[0] = a.z; v[1] = a.w;
        v[2] = b.x; v[3] = b.y; v[4] = b.z; v[5] = b.w;
    } else {
#pragma unroll
        for (int i = 0; i < 6; i++) {
            int c = px0 - 2 + i;
            v[i] = ((unsigned)c < (unsigned)W) ? __ldg(rp + c) : 0.0f;
        }
    }
}

// First-valid among 9 offsets, reference order:
// (0,0), (-1,-1),(-1,0),(-1,1),(0,-1),(0,1),(1,-1),(1,0),(1,1)
__global__ void __launch_bounds__(256) fix_kernel(const float* __restrict__ depth) {
    int idx = blockIdx.x * blockDim.x + threadIdx.x;
    if (idx >= NFIXT) return;
    int b  = idx / (FPY * TPR);
    int r  = idx - b * (FPY * TPR);
    int py = r / TPR;
    int t  = r - py * TPR;
    int px0 = t * 4;
    int y   = py - 1;

    const float* img = depth + b * (H * W);

    float m1[6], r0[6], p1[6];
    load_row6(img, y - 1, px0, m1);
    load_row6(img, y,     px0, r0);
    load_row6(img, y + 1, px0, p1);

    float ov[4];
#pragma unroll
    for (int j = 0; j < 4; j++) {
        float c[9] = { r0[j + 1],
                       m1[j], m1[j + 1], m1[j + 2],
                       r0[j],            r0[j + 2],
                       p1[j], p1[j + 1], p1[j + 2] };
        float v = 0.0f;
#pragma unroll
        for (int k = 8; k >= 0; k--) {
            if (c[k] != 0.0f) v = c[k];      // first-valid via reverse last-write
        }
        ov[j] = v;
    }
    // 4 halves = one 8B store (px0 % 4 == 0, row stride 1032B % 8 == 0)
    __half2 h01 = __floats2half2_rn(ov[0], ov[1]);
    __half2 h23 = __floats2half2_rn(ov[2], ov[3]);
    uint2 u;
    u.x = *(const unsigned*)&h01;
    u.y = *(const unsigned*)&h23;
    *(uint2*)(g_fixh + (b * FPY + py) * FPX + px0) = u;
}

// ---------------- pass 2: sampler with batch-affinity ----------------
__device__ __forceinline__ void do_quad(const __half* __restrict__ fixp, int q,
                                        float4 ga, float4 gb,
                                        float4* __restrict__ out) {
    float gx[4] = {ga.x, ga.z, gb.x, gb.z};
    float gy[4] = {ga.y, ga.w, gb.y, gb.w};
    float v[4];
#pragma unroll
    for (int i = 0; i < 4; i++) {
        // ((g+1)*0.5)*511 == round_fp32(g+1) * 255.5 exactly (×0.5 exact);
        // __float2int_rn = ties-to-even = jnp.round
        float xf = __fmul_rn(__fadd_rn(gx[i], 1.0f), 255.5f);
        float yf = __fmul_rn(__fadd_rn(gy[i], 1.0f), 255.5f);
        int ix = __float2int_rn(xf) + 1;      // padded coords
        int iy = __float2int_rn(yf) + 1;
        bool inb = ((unsigned)ix < 514u) & ((unsigned)iy < 514u);
        v[i] = inb ? __half2float(__ldg(fixp + iy * FPX + ix)) : 0.0f;
    }
    float4 o = {v[0], v[1], v[2], v[3]};
    __stcs(out + q, o);
}

// Batch-affinity: classic launches place CTAs with equal (bid % 148) on the
// same SM, so batch = (bid % 148) & 7 gives every SM a SINGLE 531 KB fp16
// map slice -> ~40% of gathers hit L1 instead of costing L2 sectors.
// Grid loads use .cg (L2-only) so streaming never evicts the map from L1.
__global__ void __launch_bounds__(SAMPLE_THREADS)
sample_kernel(const float4* __restrict__ grid, float4* __restrict__ out) {
    int r = blockIdx.x % 148;
    int k = blockIdx.x / 148;            // 0..5
    int b = r & 7;                       // this CTA's batch
    int mb = (b < 4) ? 19 : 18;          // #r-values mapping to batch b
    int j = k * mb + (r >> 3);           // CTA index within batch
    int stride = 6 * mb * SAMPLE_THREADS;

    const __half* fixp = g_fixh + b * (FPY * FPX);
    int qbase = b * QPB;

    int q = j * SAMPLE_THREADS + threadIdx.x;   // within-batch quad index
    if (q >= QPB) return;

    float4 ga = __ldcg(grid + 2 * (qbase + q));
    float4 gb = __ldcg(grid + 2 * (qbase + q) + 1);

    int qn = q + stride;
    while (qn < QPB) {
        float4 na = __ldcg(grid + 2 * (qbase + qn));   // prefetch next
        float4 nb = __ldcg(grid + 2 * (qbase + qn) + 1);
        do_quad(fixp, qbase + q, ga, gb, out);
        q = qn; qn += stride;
        ga = na; gb = nb;
    }
    do_quad(fixp, qbase + q, ga, gb, out);
}

extern "C" void kernel_launch(void* const* d_in, const int* in_sizes, int n_in,
                              void* d_out, int out_size) {
    const float*  depth = (const float*)d_in[0];   // (B,1,H,W) f32
    const float4* grid  = (const float4*)d_in[1];  // (B,Ho,Wo,2) f32 as float4
    float4*       out   = (float4*)d_out;          // (B,1,Ho,Wo) f32 as float4

    fix_kernel<<<(NFIXT + 255) / 256, 256>>>(depth);
    sample_kernel<<<SAMPLE_BLOCKS, SAMPLE_THREADS>>>(grid, out);
}

// round 10
// speedup vs baseline: 1.1614x; 1.0307x over previous
#include <cuda_runtime.h>

// Problem shapes (fixed by the dataset)
constexpr int B  = 8;
constexpr int H  = 512, W  = 512;
constexpr int HO = 1024, WO = 1024;
constexpr int FPY = 514;             // padded rows: y coords -1..512
constexpr int FPX = 516;             // padded row stride (514 valid + 2 pad, float4-aligned)
constexpr int TPR = 129;             // fix col-groups per row (129*4 = 516)
constexpr int NPIX = B * HO * WO;    // 8388608 output pixels
constexpr int NQUAD = NPIX / 4;      // 2097152 = 2^21 output quads
constexpr int NFIXT = B * FPY * TPR;

// Exact-balance single wave: 1024 CTAs (7/SM) * 256 thr * 8 quads = 2^21 = NQUAD.
constexpr int SCTAS   = 1024;
constexpr int STH     = 256;
constexpr int SSTRIDE = SCTAS * STH;           // 262144
constexpr int SITERS  = NQUAD / SSTRIDE;       // 8, exact

// Precomputed "fixed" depth map, padded domain. 8*514*516*4 B = 8.49 MB (L2-resident).
__device__ float4 g_fix4[B * FPY * (FPX / 4)];

// ---------------- pass 1: fix map (R2 form — best measured) ----------------
// Load 6 input floats covering columns [px0-2, px0+3] of `row` (0 if OOB).
__device__ __forceinline__ void load_row6(const float* __restrict__ img, int row,
                                          int px0, float v[6]) {
    if ((unsigned)row >= (unsigned)H) {
        v[0] = v[1] = v[2] = v[3] = v[4] = v[5] = 0.0f;
        return;
    }
    const float* rp = img + row * W;
    if (px0 >= 4 && px0 <= 508) {
        float4 a = *(const float4*)(rp + px0 - 4);
        float4 b = *(const float4*)(rp + px0);
        v[0] = a.z; v[1] = a.w;
        v[2] = b.x; v[3] = b.y; v[4] = b.z; v[5] = b.w;
    } else {
#pragma unroll
        for (int i = 0; i < 6; i++) {
            int c = px0 - 2 + i;
            v[i] = ((unsigned)c < (unsigned)W) ? __ldg(rp + c) : 0.0f;
        }
    }
}

// First-valid among 9 offsets, reference order:
// (0,0), (-1,-1),(-1,0),(-1,1),(0,-1),(0,1),(1,-1),(1,0),(1,1)
__global__ void __launch_bounds__(256) fix_kernel(const float* __restrict__ depth) {
    int idx = blockIdx.x * blockDim.x + threadIdx.x;
    if (idx >= NFIXT) return;
    int b  = idx / (FPY * TPR);
    int r  = idx - b * (FPY * TPR);
    int py = r / TPR;
    int t  = r - py * TPR;
    int px0 = t * 4;
    int y   = py - 1;

    const float* img = depth + b * (H * W);

    float m1[6], r0[6], p1[6];
    load_row6(img, y - 1, px0, m1);
    load_row6(img, y,     px0, r0);
    load_row6(img, y + 1, px0, p1);

    float4 o;
    float* op = &o.x;
#pragma unroll
    for (int j = 0; j < 4; j++) {
        float c[9] = { r0[j + 1],
                       m1[j], m1[j + 1], m1[j + 2],
                       r0[j],            r0[j + 2],
                       p1[j], p1[j + 1], p1[j + 2] };
        float v = 0.0f;
#pragma unroll
        for (int k = 8; k >= 0; k--) {
            if (c[k] != 0.0f) v = c[k];      // first-valid via reverse last-write
        }
        op[j] = v;
    }
    g_fix4[(b * FPY + py) * (FPX / 4) + t] = o;
}

// ---------------- pass 2: sampler ----------------
__device__ __forceinline__ void do_quad(int q, float4 ga, float4 gb,
                                        float4* __restrict__ out) {
    int b = q >> 18;                          // quads never span batches (HO*WO = 1<<20)
    const float* fixp = (const float*)g_fix4 + b * (FPY * FPX);
    float gx[4] = {ga.x, ga.z, gb.x, gb.z};
    float gy[4] = {ga.y, ga.w, gb.y, gb.w};
    float v[4];
#pragma unroll
    for (int i = 0; i < 4; i++) {
        // ((g+1)*0.5)*511 == round_fp32(g+1) * 255.5 exactly (×0.5 exact);
        // __float2int_rn = ties-to-even = jnp.round
        float xf = __fmul_rn(__fadd_rn(gx[i], 1.0f), 255.5f);
        float yf = __fmul_rn(__fadd_rn(gy[i], 1.0f), 255.5f);
        int ix = __float2int_rn(xf) + 1;      // padded coords
        int iy = __float2int_rn(yf) + 1;
        bool inb = ((unsigned)ix < 514u) & ((unsigned)iy < 514u);
        v[i] = inb ? __ldg(fixp + iy * FPX + ix) : 0.0f;
    }
    float4 o = {v[0], v[1], v[2], v[3]};
    __stcs(out + q, o);
}

// Exactly 8 quads/thread, single resident wave (7 CTAs/SM), no bounds checks.
// Next iteration's grid is prefetched while the current 4 gathers are in
// flight; in-flight gathers per thread stays at the proven depth of 4.
__global__ void __launch_bounds__(STH)
sample_kernel(const float4* __restrict__ grid, float4* __restrict__ out) {
    int q = blockIdx.x * STH + threadIdx.x;

    float4 ga = __ldcs(grid + 2 * q);
    float4 gb = __ldcs(grid + 2 * q + 1);

#pragma unroll
    for (int i = 0; i < SITERS - 1; i++) {
        float4 na = __ldcs(grid + 2 * (q + SSTRIDE));      // prefetch next
        float4 nb = __ldcs(grid + 2 * (q + SSTRIDE) + 1);
        do_quad(q, ga, gb, out);
        q += SSTRIDE;
        ga = na; gb = nb;
    }
    do_quad(q, ga, gb, out);
}

extern "C" void kernel_launch(void* const* d_in, const int* in_sizes, int n_in,
                              void* d_out, int out_size) {
    const float*  depth = (const float*)d_in[0];   // (B,1,H,W) f32
    const float4* grid  = (const float4*)d_in[1];  // (B,Ho,Wo,2) f32 as float4
    float4*       out   = (float4*)d_out;          // (B,1,Ho,Wo) f32 as float4

    fix_kernel<<<(NFIXT + 255) / 256, 256>>>(depth);
    sample_kernel<<<SCTAS, STH>>>(grid, out);
}